// round 14
// baseline (speedup 1.0000x reference)
#include <cuda_runtime.h>
#include <math.h>
#include <stdint.h>

// Problem constants (fixed: B=8, S=2048, H=8, D=64)
#define TT   16384
#define EE   512
#define HH   8
#define SS   2048
#define BB   8
#define NT   64
#define N4   2048
#define ALPHA 0.125f

// Scratch
__device__ float g_xn  [TT * EE];
__device__ float g_mix [TT * N4];
__device__ float g_att [TT * EE];
__device__ float g_par [TT * EE];
__device__ float g_wuT [N4 * EE];
__device__ float g_wpT [EE * EE];
__device__ float g_vT  [BB * HH * 64 * SS];   // V transposed: [(b,h,d)][s]

// ---------------------------------------------------------------------------
__device__ __forceinline__ uint32_t smem_u32(const void* p) {
    uint32_t a;
    asm("{ .reg .u64 t; cvta.to.shared.u64 t, %1; cvt.u32.u64 %0, t; }"
        : "=r"(a) : "l"(p));
    return a;
}
__device__ __forceinline__ float tf32_rna(float x) {
    uint32_t u = __float_as_uint(x);
    asm("cvt.rna.tf32.f32 %0, %1;" : "=r"(u) : "r"(u));
    return __uint_as_float(u);
}
__device__ __forceinline__ void mma_tf32(float* c, const uint32_t* a, const uint32_t* b) {
    asm volatile(
        "mma.sync.aligned.m16n8k8.row.col.f32.tf32.tf32.f32 "
        "{%0,%1,%2,%3}, {%4,%5,%6,%7}, {%8,%9}, {%0,%1,%2,%3};"
        : "+f"(c[0]), "+f"(c[1]), "+f"(c[2]), "+f"(c[3])
        : "r"(a[0]), "r"(a[1]), "r"(a[2]), "r"(a[3]), "r"(b[0]), "r"(b[1]));
}
__device__ __forceinline__ void ldsm_x4(uint32_t& r0, uint32_t& r1,
                                        uint32_t& r2, uint32_t& r3, uint32_t addr) {
    asm volatile("ldmatrix.sync.aligned.m8n8.x4.shared.b16 {%0,%1,%2,%3}, [%4];"
                 : "=r"(r0), "=r"(r1), "=r"(r2), "=r"(r3) : "r"(addr));
}
#define CP_ASYNC16(s, g) asm volatile("cp.async.cg.shared.global [%0], [%1], 16;" :: "r"(s), "l"(g))
#define CP_COMMIT()      asm volatile("cp.async.commit_group;")
#define CP_WAIT1()       asm volatile("cp.async.wait_group 1;" ::: "memory")
#define CP_WAIT0()       asm volatile("cp.async.wait_group 0;" ::: "memory")

// ldmatrix lane offsets for padded-stride tiles, stride in floats
__device__ __forceinline__ uint32_t lda_off(int baserow, int stride, int lane) {
    int r15 = lane & 15, c4 = (lane >> 4) * 4;
    return (uint32_t)(((baserow + r15) * stride + c4) * 4);
}
__device__ __forceinline__ uint32_t ldb_off(int baserow, int stride, int lane) {
    int r7 = lane & 7, sel = lane >> 3;
    return (uint32_t)(((baserow + r7 + (sel >> 1) * 8) * stride + (sel & 1) * 4) * 4);
}

// Accumulator (16x8, [g][2t]) -> A-fragment ([g][t],[g][t+4]) in-warp transpose.
// Target lane (g,t) takes column t from lane (g, t>>1) reg c[t&1] etc.
__device__ __forceinline__ void acc_to_afrag(uint32_t* a, const float* c, int lane) {
    int srcA = (lane & 28) | ((lane & 3) >> 1);
    int srcB = srcA + 2;
    bool odd = (lane & 1);
    float v00 = __shfl_sync(0xffffffffu, c[0], srcA);
    float v01 = __shfl_sync(0xffffffffu, c[1], srcA);
    float v02 = __shfl_sync(0xffffffffu, c[2], srcA);
    float v03 = __shfl_sync(0xffffffffu, c[3], srcA);
    float v10 = __shfl_sync(0xffffffffu, c[0], srcB);
    float v11 = __shfl_sync(0xffffffffu, c[1], srcB);
    float v12 = __shfl_sync(0xffffffffu, c[2], srcB);
    float v13 = __shfl_sync(0xffffffffu, c[3], srcB);
    a[0] = __float_as_uint(odd ? v01 : v00);
    a[1] = __float_as_uint(odd ? v03 : v02);
    a[2] = __float_as_uint(odd ? v11 : v10);
    a[3] = __float_as_uint(odd ? v13 : v12);
}

// ---------------------------------------------------------------------------
// Weight transpose + tf32 rounding: dst[n][k] = rna(src[k][n])
// ---------------------------------------------------------------------------
__global__ void transpose_kernel(const float* __restrict__ src,
                                 float* __restrict__ dst, int K, int N)
{
    __shared__ float t[32][33];
    int n0 = blockIdx.x * 32, k0 = blockIdx.y * 32;
    int tx = threadIdx.x, ty = threadIdx.y;
    #pragma unroll
    for (int j = 0; j < 4; j++)
        t[ty + j * 8][tx] = src[(size_t)(k0 + ty + j * 8) * N + n0 + tx];
    __syncthreads();
    #pragma unroll
    for (int j = 0; j < 4; j++)
        dst[(size_t)(n0 + ty + j * 8) * K + k0 + tx] = tf32_rna(t[tx][ty + j * 8]);
}

// v transpose: g_vT[(b*H+h)*64 + d][s] = g_mix[b*S+s][512 + h*64 + d]
__global__ void vt_kernel()
{
    __shared__ float t[32][33];
    int bh = blockIdx.z;
    int s0 = blockIdx.x * 32, d0 = blockIdx.y * 32;
    int tx = threadIdx.x, ty = threadIdx.y;
    int b = bh >> 3, h = bh & 7;
    #pragma unroll
    for (int j = 0; j < 4; j++)
        t[ty + j * 8][tx] =
            g_mix[(size_t)(b * SS + s0 + ty + j * 8) * N4 + 512 + h * 64 + d0 + tx];
    __syncthreads();
    #pragma unroll
    for (int j = 0; j < 4; j++)
        g_vT[(size_t)(bh * 64 + d0 + ty + j * 8) * SS + s0 + tx] = t[tx][ty + j * 8];
}

// ---------------------------------------------------------------------------
// LayerNorm kernels (tf32-rounded outputs)
// ---------------------------------------------------------------------------
__global__ void ln_in_kernel(const float* __restrict__ x,
                             const float* __restrict__ w,
                             const float* __restrict__ b,
                             float* __restrict__ out)
{
    int row = blockIdx.x;
    int tid = threadIdx.x;
    const float4* xr = (const float4*)(x + (size_t)row * EE);
    float4 v = xr[tid];
    float s  = v.x + v.y + v.z + v.w;
    float s2 = v.x*v.x + v.y*v.y + v.z*v.z + v.w*v.w;
    #pragma unroll
    for (int off = 16; off; off >>= 1) {
        s  += __shfl_xor_sync(0xffffffffu, s,  off);
        s2 += __shfl_xor_sync(0xffffffffu, s2, off);
    }
    __shared__ float sb[4], sb2[4];
    int wid = tid >> 5, lane = tid & 31;
    if (lane == 0) { sb[wid] = s; sb2[wid] = s2; }
    __syncthreads();
    float tot  = sb[0] + sb[1] + sb[2] + sb[3];
    float tot2 = sb2[0] + sb2[1] + sb2[2] + sb2[3];
    float mu  = tot * (1.0f / EE);
    float var = tot2 * (1.0f / EE) - mu * mu;
    float rstd = rsqrtf(var + 1e-5f);
    float4 w4 = ((const float4*)w)[tid];
    float4 b4 = ((const float4*)b)[tid];
    float4 o;
    o.x = tf32_rna((v.x - mu) * rstd * w4.x + b4.x);
    o.y = tf32_rna((v.y - mu) * rstd * w4.y + b4.y);
    o.z = tf32_rna((v.z - mu) * rstd * w4.z + b4.z);
    o.w = tf32_rna((v.w - mu) * rstd * w4.w + b4.w);
    ((float4*)(out + (size_t)row * EE))[tid] = o;
}

__global__ void ln_mul_kernel(const float* __restrict__ a,
                              const float* __restrict__ w,
                              const float* __restrict__ b,
                              float* __restrict__ out)
{
    int row = blockIdx.x;
    int tid = threadIdx.x;
    const float4* xr = (const float4*)(a + (size_t)row * EE);
    float4 v = xr[tid];
    float s  = v.x + v.y + v.z + v.w;
    float s2 = v.x*v.x + v.y*v.y + v.z*v.z + v.w*v.w;
    #pragma unroll
    for (int off = 16; off; off >>= 1) {
        s  += __shfl_xor_sync(0xffffffffu, s,  off);
        s2 += __shfl_xor_sync(0xffffffffu, s2, off);
    }
    __shared__ float sb[4], sb2[4];
    int wid = tid >> 5, lane = tid & 31;
    if (lane == 0) { sb[wid] = s; sb2[wid] = s2; }
    __syncthreads();
    float tot  = sb[0] + sb[1] + sb[2] + sb[3];
    float tot2 = sb2[0] + sb2[1] + sb2[2] + sb2[3];
    float mu  = tot * (1.0f / EE);
    float var = tot2 * (1.0f / EE) - mu * mu;
    float rstd = rsqrtf(var + 1e-5f);
    float4 w4 = ((const float4*)w)[tid];
    float4 b4 = ((const float4*)b)[tid];
    float4 u4 = ((const float4*)(g_mix + (size_t)row * N4))[tid];
    float4 o;
    o.x = tf32_rna(u4.x * ((v.x - mu) * rstd * w4.x + b4.x));
    o.y = tf32_rna(u4.y * ((v.y - mu) * rstd * w4.y + b4.y));
    o.z = tf32_rna(u4.z * ((v.z - mu) * rstd * w4.z + b4.z));
    o.w = tf32_rna(u4.w * ((v.w - mu) * rstd * w4.w + b4.w));
    ((float4*)(out + (size_t)row * EE))[tid] = o;
}

// ---------------------------------------------------------------------------
// mma.sync tf32 GEMM (R12, proven): 128x128 tile, BK=32, double-buffered
// cp.async, ldmatrix feed, 2 CTAs/SM, compile-time N/K.
// ---------------------------------------------------------------------------
#define ASTRIDE 36
#define AB0 0
#define AB1 4608
#define BB0 9216
#define BB1 13824
#define GEMM_SMEM (18432 * 4)

template<bool SILU, bool RES, bool ROUND, int NN, int KK>
__global__ void __launch_bounds__(256, 2)
gemm_mma(const float* __restrict__ A, const float* __restrict__ Bt,
         const float* __restrict__ bias, const float* __restrict__ res,
         float* __restrict__ C)
{
    extern __shared__ float sm[];
    uint32_t sbase = smem_u32(sm);
    int tid = threadIdx.x;
    int wid = tid >> 5, lane = tid & 31;
    int g = lane >> 2, t = lane & 3;
    int wm = wid >> 2, wn = wid & 3;
    int bm = blockIdx.y * 128, bn = blockIdx.x * 128;
    constexpr int NC = KK >> 5;

    uint32_t aoff[4], boff[2];
    #pragma unroll
    for (int mt = 0; mt < 4; mt++)
        aoff[mt] = lda_off(wm * 64 + mt * 16, ASTRIDE, lane);
    boff[0] = ldb_off(wn * 32,      ASTRIDE, lane);
    boff[1] = ldb_off(wn * 32 + 16, ASTRIDE, lane);

    float c[4][4][4];
    #pragma unroll
    for (int i = 0; i < 4; i++)
        #pragma unroll
        for (int j = 0; j < 4; j++)
            #pragma unroll
            for (int e = 0; e < 4; e++) c[i][j][e] = 0.0f;

    auto load_tile = [&](int koff, int buf) {
        uint32_t ab = sbase + (buf ? AB1 : AB0) * 4;
        uint32_t bb = sbase + (buf ? BB1 : BB0) * 4;
        #pragma unroll
        for (int p = 0; p < 4; p++) {
            int idx = tid + p * 256;
            int row = idx >> 3, q = idx & 7;
            CP_ASYNC16(ab + row * 144 + q * 16,
                       A + (size_t)(bm + row) * KK + koff + q * 4);
        }
        #pragma unroll
        for (int p = 0; p < 4; p++) {
            int idx = tid + p * 256;
            int row = idx >> 3, q = idx & 7;
            CP_ASYNC16(bb + row * 144 + q * 16,
                       Bt + (size_t)(bn + row) * KK + koff + q * 4);
        }
        CP_COMMIT();
    };

    load_tile(0, 0);

    #pragma unroll
    for (int i = 0; i < NC; i++) {
        if (i + 1 < NC) { load_tile((i + 1) << 5, (i + 1) & 1); CP_WAIT1(); }
        else            { CP_WAIT0(); }
        __syncthreads();

        uint32_t abuf = sbase + ((i & 1) ? AB1 : AB0) * 4;
        uint32_t bbuf = sbase + ((i & 1) ? BB1 : BB0) * 4;

        #pragma unroll
        for (int k8 = 0; k8 < 4; k8++) {
            uint32_t kb = k8 * 32;
            uint32_t a[4][4], b[4][2];
            #pragma unroll
            for (int mt = 0; mt < 4; mt++)
                ldsm_x4(a[mt][0], a[mt][1], a[mt][2], a[mt][3],
                        abuf + aoff[mt] + kb);
            ldsm_x4(b[0][0], b[0][1], b[1][0], b[1][1], bbuf + boff[0] + kb);
            ldsm_x4(b[2][0], b[2][1], b[3][0], b[3][1], bbuf + boff[1] + kb);
            #pragma unroll
            for (int mt = 0; mt < 4; mt++)
                #pragma unroll
                for (int nt = 0; nt < 4; nt++)
                    mma_tf32(c[mt][nt], a[mt], b[nt]);
        }
        __syncthreads();
    }

    // epilogue
    #pragma unroll
    for (int mt = 0; mt < 4; mt++) {
        int r0 = bm + wm * 64 + mt * 16 + g;
        #pragma unroll
        for (int nt = 0; nt < 4; nt++) {
            int col = bn + wn * 32 + nt * 8 + 2 * t;
            float bx = 0.f, by = 0.f;
            if (bias) { bx = __ldg(bias + col); by = __ldg(bias + col + 1); }
            #pragma unroll
            for (int half = 0; half < 2; half++) {
                int r = r0 + half * 8;
                float vx = c[mt][nt][half * 2 + 0] + bx;
                float vy = c[mt][nt][half * 2 + 1] + by;
                if (SILU) {
                    vx = vx / (1.0f + __expf(-vx));
                    vy = vy / (1.0f + __expf(-vy));
                }
                if (RES) {
                    float2 rr = *(const float2*)(res + (size_t)r * NN + col);
                    vx += rr.x; vy += rr.y;
                }
                if (ROUND) { vx = tf32_rna(vx); vy = tf32_rna(vy); }
                *(float2*)(C + (size_t)r * NN + col) = make_float2(vx, vy);
            }
        }
    }
}

// ---------------------------------------------------------------------------
// SiLU attention v2: S in [i][j] orientation; P stays in registers via
// in-warp fragment transpose (acc_to_afrag). ONE barrier per j-tile, no P
// smem. Each warp owns [16i x 32j] (wI = wid>>1, wJ = wid&1) and accumulates
// partial O[16i x 64d] over its j-half; cross-warp O reduction at the end.
// smem (floats, stride 68): KS0 KS1 VT0 VT1 QS RED, each 64x68
// ---------------------------------------------------------------------------
#define KS0_F 0
#define KS1_F 4352
#define VT0_F 8704
#define VT1_F 13056
#define QS_F  17408
#define RED_F 21760
#define ATT_SMEM (26112 * 4)   // 104448 B; 2 CTAs/SM

__global__ void __launch_bounds__(256, 2) attn_mma()
{
    extern __shared__ float sm[];
    uint32_t sbase = smem_u32(sm);
    int bi = (int)gridDim.x - 1 - (int)blockIdx.x;   // longest CTAs first
    int h = blockIdx.y, b = blockIdx.z;
    int tid = threadIdx.x, wid = tid >> 5, lane = tid & 31;
    int g = lane >> 2, t = lane & 3;
    int wI = wid >> 1, wJ = wid & 1;
    const int qoff = 1024 + h * 64;
    const int koff = 1536 + h * 64;
    const int ibase = bi * 64;
    const size_t rowb = (size_t)b * SS;
    const size_t vtb  = (size_t)(b * HH + h) * 64;
    const float invS = 1.0f / (float)SS;

    // fragment lane offsets (bytes)
    uint32_t a_q   = lda_off(wI * 16, 68, lane);         // Q rows i
    uint32_t b_k0  = ldb_off(wJ * 32,      68, lane);    // K rows j
    uint32_t b_k1  = ldb_off(wJ * 32 + 16, 68, lane);
    uint32_t b_v[4];
    #pragma unroll
    for (int p = 0; p < 4; p++) b_v[p] = ldb_off(p * 16, 68, lane);  // V^T rows d
    const uint32_t pv_kbase = (uint32_t)(wJ * 128);      // k(j) byte base for PV

    auto load_kv = [&](int jbase, int buf) {
        uint32_t kb = sbase + (buf ? KS1_F : KS0_F) * 4;
        uint32_t vb = sbase + (buf ? VT1_F : VT0_F) * 4;
        #pragma unroll
        for (int p = 0; p < 4; p++) {
            int idx = tid + p * 256;
            int row = idx >> 4, c16 = idx & 15;
            CP_ASYNC16(kb + row * 272 + c16 * 16,
                       g_mix + (rowb + jbase + row) * (size_t)N4 + koff + c16 * 4);
            CP_ASYNC16(vb + row * 272 + c16 * 16,
                       g_vT + (vtb + row) * SS + jbase + c16 * 4);
        }
        CP_COMMIT();
    };

    load_kv(0, 0);
    {
        uint32_t qb = sbase + QS_F * 4;
        #pragma unroll
        for (int p = 0; p < 4; p++) {
            int idx = tid + p * 256;
            int row = idx >> 4, c16 = idx & 15;
            CP_ASYNC16(qb + row * 272 + c16 * 16,
                       g_mix + (rowb + ibase + row) * (size_t)N4 + qoff + c16 * 4);
        }
        CP_COMMIT();
    }

    float o[8][4];   // partial O[16i x 64d] over this warp's j-half
    #pragma unroll
    for (int nt = 0; nt < 8; nt++)
        #pragma unroll
        for (int e = 0; e < 4; e++) o[nt][e] = 0.0f;

    for (int jt = 0; jt <= bi; jt++) {
        int jbase = jt * 64;
        int cur = jt & 1;
        uint32_t ksb = sbase + (cur ? KS1_F : KS0_F) * 4;
        uint32_t vsb = sbase + (cur ? VT1_F : VT0_F) * 4;
        uint32_t qsb = sbase + QS_F * 4;

        CP_WAIT0();
        __syncthreads();   // K/V[cur] (+Q on jt=0) visible; all warps past jt-1

        // prefetch next tile — overlaps ALL of this tile's compute
        if (jt < bi) load_kv(jbase + 64, cur ^ 1);

        // QK: c[nt] = S tile [wI*16 i][wJ*32 + nt*8 j], k = d (64)
        float c[4][4];
        #pragma unroll
        for (int nt = 0; nt < 4; nt++)
            #pragma unroll
            for (int e = 0; e < 4; e++) c[nt][e] = 0.0f;

        #pragma unroll
        for (int k8 = 0; k8 < 8; k8++) {
            uint32_t kb = k8 * 32;
            uint32_t a[4], bfr[4][2];
            ldsm_x4(a[0], a[1], a[2], a[3], qsb + a_q + kb);
            ldsm_x4(bfr[0][0], bfr[0][1], bfr[1][0], bfr[1][1], ksb + b_k0 + kb);
            ldsm_x4(bfr[2][0], bfr[2][1], bfr[3][0], bfr[3][1], ksb + b_k1 + kb);
            #pragma unroll
            for (int nt = 0; nt < 4; nt++)
                mma_tf32(c[nt], a, bfr[nt]);
        }

        // silu + mask (diagonal tile only), tf32-round; P stays in registers
        bool diag = (jt == bi);
        #pragma unroll
        for (int nt = 0; nt < 4; nt++) {
            #pragma unroll
            for (int e = 0; e < 4; e++) {
                float z = c[nt][e] * ALPHA;
                float sv = z / (1.0f + __expf(-z)) * invS;
                if (diag) {
                    int gi = ibase + wI * 16 + g + (e >> 1) * 8;
                    int gj = jbase + wJ * 32 + nt * 8 + 2 * t + (e & 1);
                    bool valid = (gj <= gi) && ((gj < SS - NT) || (gi == gj));
                    sv = valid ? sv : 0.0f;
                }
                c[nt][e] = tf32_rna(sv);
            }
        }

        // PV: O[16i x 64d] += P[16i x 32j] @ V[32j x 64d]  (k = this warp's j)
        #pragma unroll
        for (int nt = 0; nt < 4; nt++) {
            uint32_t a[4];
            acc_to_afrag(a, c[nt], lane);            // P fragment, no smem
            uint32_t kb = pv_kbase + nt * 32;        // k(j) byte offset in VT
            uint32_t bfr[8][2];
            #pragma unroll
            for (int p = 0; p < 4; p++)
                ldsm_x4(bfr[2*p][0], bfr[2*p][1], bfr[2*p+1][0], bfr[2*p+1][1],
                        vsb + b_v[p] + kb);
            #pragma unroll
            for (int dt = 0; dt < 8; dt++)
                mma_tf32(o[dt], a, bfr[dt]);
        }
    }

    // cross-warp O reduction: wJ=1 warps stage to smem, wJ=0 add + write
    __syncthreads();
    if (wJ == 1) {
        #pragma unroll
        for (int dt = 0; dt < 8; dt++)
            #pragma unroll
            for (int half = 0; half < 2; half++)
                *(float2*)(sm + RED_F + (wI * 16 + g + half * 8) * 68
                           + dt * 8 + 2 * t) =
                    make_float2(o[dt][half * 2 + 0], o[dt][half * 2 + 1]);
    }
    __syncthreads();
    if (wJ == 0) {
        #pragma unroll
        for (int dt = 0; dt < 8; dt++) {
            int col = h * 64 + dt * 8 + 2 * t;
            #pragma unroll
            for (int half = 0; half < 2; half++) {
                float2 r2 = *(const float2*)(sm + RED_F +
                             (wI * 16 + g + half * 8) * 68 + dt * 8 + 2 * t);
                size_t r = rowb + ibase + wI * 16 + g + half * 8;
                *(float2*)(g_att + r * EE + col) =
                    make_float2(o[dt][half * 2 + 0] + r2.x,
                                o[dt][half * 2 + 1] + r2.y);
            }
        }
    }
}

// ---------------------------------------------------------------------------
extern "C" void kernel_launch(void* const* d_in, const int* in_sizes, int n_in,
                              void* d_out, int out_size)
{
    const float* x       = (const float*)d_in[0];
    const float* w_uvqk  = (const float*)d_in[1];
    const float* b_uvqk  = (const float*)d_in[2];
    const float* ln_in_w = (const float*)d_in[3];
    const float* ln_in_b = (const float*)d_in[4];
    const float* ln_o_w  = (const float*)d_in[5];
    const float* ln_o_b  = (const float*)d_in[6];
    const float* w_proj  = (const float*)d_in[7];
    float* out = (float*)d_out;

    float *xn, *mix, *att, *par, *wuT, *wpT;
    cudaGetSymbolAddress((void**)&xn,  g_xn);
    cudaGetSymbolAddress((void**)&mix, g_mix);
    cudaGetSymbolAddress((void**)&att, g_att);
    cudaGetSymbolAddress((void**)&par, g_par);
    cudaGetSymbolAddress((void**)&wuT, g_wuT);
    cudaGetSymbolAddress((void**)&wpT, g_wpT);

    cudaFuncSetAttribute(gemm_mma<true, false, true, N4, EE>,
                         cudaFuncAttributeMaxDynamicSharedMemorySize, GEMM_SMEM);
    cudaFuncSetAttribute(gemm_mma<false, true, false, EE, EE>,
                         cudaFuncAttributeMaxDynamicSharedMemorySize, GEMM_SMEM);
    cudaFuncSetAttribute(attn_mma,
                         cudaFuncAttributeMaxDynamicSharedMemorySize, ATT_SMEM);

    // weight transposes (tf32-rounded)
    {
        dim3 b32(32, 8);
        transpose_kernel<<<dim3(N4 / 32, EE / 32), b32>>>(w_uvqk, wuT, EE, N4);
        transpose_kernel<<<dim3(EE / 32, EE / 32), b32>>>(w_proj, wpT, EE, EE);
    }

    // 1) input LN
    ln_in_kernel<<<TT, 128>>>(x, ln_in_w, ln_in_b, xn);

    // 2) mixed = silu(xn @ w_uvqk + b)  -> tf32-rounded
    {
        dim3 grid(N4 / 128, TT / 128);
        gemm_mma<true, false, true, N4, EE><<<grid, 256, GEMM_SMEM>>>(
            xn, wuT, b_uvqk, nullptr, mix);
    }

    // 2b) v transpose for attention PV ldmatrix
    {
        dim3 b32(32, 8);
        vt_kernel<<<dim3(SS / 32, 2, BB * HH), b32>>>();
    }

    // 3) attention (64-query tiles, 1 barrier/tile, register-resident P)
    {
        dim3 grid(SS / 64, HH, BB);
        attn_mma<<<grid, 256, ATT_SMEM>>>();
    }

    // 4) parallel = u * LN(attn_out)
    ln_mul_kernel<<<TT, 128>>>(att, ln_o_w, ln_o_b, par);

    // 5) out = parallel @ w_proj + x
    {
        dim3 grid(EE / 128, TT / 128);
        gemm_mma<false, true, false, EE, EE><<<grid, 256, GEMM_SMEM>>>(
            par, wpT, nullptr, x, out);
    }
}

// round 15
// speedup vs baseline: 1.6566x; 1.6566x over previous
#include <cuda_runtime.h>
#include <math.h>
#include <stdint.h>

// Problem constants (fixed: B=8, S=2048, H=8, D=64)
#define TT   16384
#define EE   512
#define HH   8
#define SS   2048
#define BB   8
#define NT   64
#define N4   2048
#define ALPHA 0.125f

// Scratch
__device__ float g_xn  [TT * EE];
__device__ float g_mix [TT * N4];
__device__ float g_att [TT * EE];
__device__ float g_par [TT * EE];
__device__ float g_wuT [N4 * EE];
__device__ float g_wpT [EE * EE];
__device__ float g_vT  [BB * HH * 64 * SS];   // V transposed: [(b,h,d)][s]

// ---------------------------------------------------------------------------
__device__ __forceinline__ uint32_t smem_u32(const void* p) {
    uint32_t a;
    asm("{ .reg .u64 t; cvta.to.shared.u64 t, %1; cvt.u32.u64 %0, t; }"
        : "=r"(a) : "l"(p));
    return a;
}
__device__ __forceinline__ float tf32_rna(float x) {
    uint32_t u = __float_as_uint(x);
    asm("cvt.rna.tf32.f32 %0, %1;" : "=r"(u) : "r"(u));
    return __uint_as_float(u);
}
__device__ __forceinline__ void mma_tf32(float* c, const uint32_t* a, const uint32_t* b) {
    asm volatile(
        "mma.sync.aligned.m16n8k8.row.col.f32.tf32.tf32.f32 "
        "{%0,%1,%2,%3}, {%4,%5,%6,%7}, {%8,%9}, {%0,%1,%2,%3};"
        : "+f"(c[0]), "+f"(c[1]), "+f"(c[2]), "+f"(c[3])
        : "r"(a[0]), "r"(a[1]), "r"(a[2]), "r"(a[3]), "r"(b[0]), "r"(b[1]));
}
__device__ __forceinline__ void ldsm_x4(uint32_t& r0, uint32_t& r1,
                                        uint32_t& r2, uint32_t& r3, uint32_t addr) {
    asm volatile("ldmatrix.sync.aligned.m8n8.x4.shared.b16 {%0,%1,%2,%3}, [%4];"
                 : "=r"(r0), "=r"(r1), "=r"(r2), "=r"(r3) : "r"(addr));
}
#define CP_ASYNC16(s, g) asm volatile("cp.async.cg.shared.global [%0], [%1], 16;" :: "r"(s), "l"(g))
#define CP_COMMIT()      asm volatile("cp.async.commit_group;")
#define CP_WAIT1()       asm volatile("cp.async.wait_group 1;" ::: "memory")
#define CP_WAIT0()       asm volatile("cp.async.wait_group 0;" ::: "memory")

// ldmatrix lane offsets for padded-stride tiles, stride in floats
__device__ __forceinline__ uint32_t lda_off(int baserow, int stride, int lane) {
    int r15 = lane & 15, c4 = (lane >> 4) * 4;
    return (uint32_t)(((baserow + r15) * stride + c4) * 4);
}
__device__ __forceinline__ uint32_t ldb_off(int baserow, int stride, int lane) {
    int r7 = lane & 7, sel = lane >> 3;
    return (uint32_t)(((baserow + r7 + (sel >> 1) * 8) * stride + (sel & 1) * 4) * 4);
}

// Accumulator (16x8, [g][2t]) -> A-fragment ([g][t],[g][t+4]) in-warp transpose.
__device__ __forceinline__ void acc_to_afrag(uint32_t* a, const float* c, int lane) {
    int srcA = (lane & 28) | ((lane & 3) >> 1);
    int srcB = srcA + 2;
    bool odd = (lane & 1);
    float v00 = __shfl_sync(0xffffffffu, c[0], srcA);
    float v01 = __shfl_sync(0xffffffffu, c[1], srcA);
    float v02 = __shfl_sync(0xffffffffu, c[2], srcA);
    float v03 = __shfl_sync(0xffffffffu, c[3], srcA);
    float v10 = __shfl_sync(0xffffffffu, c[0], srcB);
    float v11 = __shfl_sync(0xffffffffu, c[1], srcB);
    float v12 = __shfl_sync(0xffffffffu, c[2], srcB);
    float v13 = __shfl_sync(0xffffffffu, c[3], srcB);
    a[0] = __float_as_uint(odd ? v01 : v00);
    a[1] = __float_as_uint(odd ? v03 : v02);
    a[2] = __float_as_uint(odd ? v11 : v10);
    a[3] = __float_as_uint(odd ? v13 : v12);
}

// ---------------------------------------------------------------------------
// Weight transpose + tf32 rounding: dst[n][k] = rna(src[k][n])
// ---------------------------------------------------------------------------
__global__ void transpose_kernel(const float* __restrict__ src,
                                 float* __restrict__ dst, int K, int N)
{
    __shared__ float t[32][33];
    int n0 = blockIdx.x * 32, k0 = blockIdx.y * 32;
    int tx = threadIdx.x, ty = threadIdx.y;
    #pragma unroll
    for (int j = 0; j < 4; j++)
        t[ty + j * 8][tx] = src[(size_t)(k0 + ty + j * 8) * N + n0 + tx];
    __syncthreads();
    #pragma unroll
    for (int j = 0; j < 4; j++)
        dst[(size_t)(n0 + ty + j * 8) * K + k0 + tx] = tf32_rna(t[tx][ty + j * 8]);
}

// v transpose: g_vT[(b*H+h)*64 + d][s] = g_mix[b*S+s][512 + h*64 + d]
__global__ void vt_kernel()
{
    __shared__ float t[32][33];
    int bh = blockIdx.z;
    int s0 = blockIdx.x * 32, d0 = blockIdx.y * 32;
    int tx = threadIdx.x, ty = threadIdx.y;
    int b = bh >> 3, h = bh & 7;
    #pragma unroll
    for (int j = 0; j < 4; j++)
        t[ty + j * 8][tx] =
            g_mix[(size_t)(b * SS + s0 + ty + j * 8) * N4 + 512 + h * 64 + d0 + tx];
    __syncthreads();
    #pragma unroll
    for (int j = 0; j < 4; j++)
        g_vT[(size_t)(bh * 64 + d0 + ty + j * 8) * SS + s0 + tx] = t[tx][ty + j * 8];
}

// ---------------------------------------------------------------------------
// LayerNorm kernels (tf32-rounded outputs)
// ---------------------------------------------------------------------------
__global__ void ln_in_kernel(const float* __restrict__ x,
                             const float* __restrict__ w,
                             const float* __restrict__ b,
                             float* __restrict__ out)
{
    int row = blockIdx.x;
    int tid = threadIdx.x;
    const float4* xr = (const float4*)(x + (size_t)row * EE);
    float4 v = xr[tid];
    float s  = v.x + v.y + v.z + v.w;
    float s2 = v.x*v.x + v.y*v.y + v.z*v.z + v.w*v.w;
    #pragma unroll
    for (int off = 16; off; off >>= 1) {
        s  += __shfl_xor_sync(0xffffffffu, s,  off);
        s2 += __shfl_xor_sync(0xffffffffu, s2, off);
    }
    __shared__ float sb[4], sb2[4];
    int wid = tid >> 5, lane = tid & 31;
    if (lane == 0) { sb[wid] = s; sb2[wid] = s2; }
    __syncthreads();
    float tot  = sb[0] + sb[1] + sb[2] + sb[3];
    float tot2 = sb2[0] + sb2[1] + sb2[2] + sb2[3];
    float mu  = tot * (1.0f / EE);
    float var = tot2 * (1.0f / EE) - mu * mu;
    float rstd = rsqrtf(var + 1e-5f);
    float4 w4 = ((const float4*)w)[tid];
    float4 b4 = ((const float4*)b)[tid];
    float4 o;
    o.x = tf32_rna((v.x - mu) * rstd * w4.x + b4.x);
    o.y = tf32_rna((v.y - mu) * rstd * w4.y + b4.y);
    o.z = tf32_rna((v.z - mu) * rstd * w4.z + b4.z);
    o.w = tf32_rna((v.w - mu) * rstd * w4.w + b4.w);
    ((float4*)(out + (size_t)row * EE))[tid] = o;
}

__global__ void ln_mul_kernel(const float* __restrict__ a,
                              const float* __restrict__ w,
                              const float* __restrict__ b,
                              float* __restrict__ out)
{
    int row = blockIdx.x;
    int tid = threadIdx.x;
    const float4* xr = (const float4*)(a + (size_t)row * EE);
    float4 v = xr[tid];
    float s  = v.x + v.y + v.z + v.w;
    float s2 = v.x*v.x + v.y*v.y + v.z*v.z + v.w*v.w;
    #pragma unroll
    for (int off = 16; off; off >>= 1) {
        s  += __shfl_xor_sync(0xffffffffu, s,  off);
        s2 += __shfl_xor_sync(0xffffffffu, s2, off);
    }
    __shared__ float sb[4], sb2[4];
    int wid = tid >> 5, lane = tid & 31;
    if (lane == 0) { sb[wid] = s; sb2[wid] = s2; }
    __syncthreads();
    float tot  = sb[0] + sb[1] + sb[2] + sb[3];
    float tot2 = sb2[0] + sb2[1] + sb2[2] + sb2[3];
    float mu  = tot * (1.0f / EE);
    float var = tot2 * (1.0f / EE) - mu * mu;
    float rstd = rsqrtf(var + 1e-5f);
    float4 w4 = ((const float4*)w)[tid];
    float4 b4 = ((const float4*)b)[tid];
    float4 u4 = ((const float4*)(g_mix + (size_t)row * N4))[tid];
    float4 o;
    o.x = tf32_rna(u4.x * ((v.x - mu) * rstd * w4.x + b4.x));
    o.y = tf32_rna(u4.y * ((v.y - mu) * rstd * w4.y + b4.y));
    o.z = tf32_rna(u4.z * ((v.z - mu) * rstd * w4.z + b4.z));
    o.w = tf32_rna(u4.w * ((v.w - mu) * rstd * w4.w + b4.w));
    ((float4*)(out + (size_t)row * EE))[tid] = o;
}

// ---------------------------------------------------------------------------
// mma.sync tf32 GEMM (R9 swizzled 3-stage + R12 compile-time unroll):
//   128x128 tile, BK=32, 8 warps, ldmatrix feed, 1 syncthreads per chunk.
//   Tiles: 128 rows x 32 floats (128B rows), 16B granule XOR-swizzled by row&7.
// ---------------------------------------------------------------------------
#define GSTAGE_B 32768              // bytes per stage (A 16K + B 16K)
#define GEMM_SMEM (3 * GSTAGE_B)    // 98304 B -> 2 CTAs/SM

template<bool SILU, bool RES, bool ROUND, int NN, int KK>
__global__ void __launch_bounds__(256, 2)
gemm_mma(const float* __restrict__ A, const float* __restrict__ Bt,
         const float* __restrict__ bias, const float* __restrict__ res,
         float* __restrict__ C)
{
    extern __shared__ float sm[];
    uint32_t sbase = smem_u32(sm);
    int tid = threadIdx.x;
    int wid = tid >> 5, lane = tid & 31;
    int g = lane >> 2, t = lane & 3;
    int wm = wid >> 2, wn = wid & 3;
    int bm = blockIdx.y * 128, bn = blockIdx.x * 128;
    constexpr int NC = KK >> 5;

    // swizzled ldmatrix addressing precompute
    uint32_t abase[4], asw[4];
    uint32_t agsel = (uint32_t)(lane >> 4);       // 0/1
    #pragma unroll
    for (int mt = 0; mt < 4; mt++) {
        int r = wm * 64 + mt * 16 + (lane & 15);
        abase[mt] = (uint32_t)(r * 128);
        asw[mt]   = (uint32_t)(r & 7);
    }
    uint32_t bbase[2], bsw[2], bg0;
    {
        int sel = lane >> 3;
        bg0 = (uint32_t)(sel & 1);
        #pragma unroll
        for (int p = 0; p < 2; p++) {
            int r = wn * 32 + p * 16 + (lane & 7) + ((sel >> 1) * 8);
            bbase[p] = (uint32_t)(r * 128);
            bsw[p]   = (uint32_t)(r & 7);
        }
    }

    float c[4][4][4];
    #pragma unroll
    for (int i = 0; i < 4; i++)
        #pragma unroll
        for (int j = 0; j < 4; j++)
            #pragma unroll
            for (int e = 0; e < 4; e++) c[i][j][e] = 0.0f;

    auto load_tile = [&](int koff, int stage) {
        uint32_t ab = sbase + stage * GSTAGE_B;
        uint32_t bb = ab + 16384;
        #pragma unroll
        for (int p = 0; p < 4; p++) {
            int idx = tid + p * 256;
            int row = idx >> 3, c16 = idx & 7;
            uint32_t so = (uint32_t)(row * 128 + ((c16 ^ (row & 7)) << 4));
            CP_ASYNC16(ab + so, A + (size_t)(bm + row) * KK + koff + c16 * 4);
        }
        #pragma unroll
        for (int p = 0; p < 4; p++) {
            int idx = tid + p * 256;
            int row = idx >> 3, c16 = idx & 7;
            uint32_t so = (uint32_t)(row * 128 + ((c16 ^ (row & 7)) << 4));
            CP_ASYNC16(bb + so, Bt + (size_t)(bn + row) * KK + koff + c16 * 4);
        }
        CP_COMMIT();
    };

    load_tile(0, 0);
    load_tile(32, 1);

    #pragma unroll
    for (int i = 0; i < NC; i++) {
        const int stage = i % 3;
        if (i + 1 < NC) CP_WAIT1(); else CP_WAIT0();
        __syncthreads();

        uint32_t abuf = sbase + stage * GSTAGE_B;
        uint32_t bbuf = abuf + 16384;

        #pragma unroll
        for (int k8 = 0; k8 < 4; k8++) {
            uint32_t a[4][4], b[4][2];
            #pragma unroll
            for (int mt = 0; mt < 4; mt++)
                ldsm_x4(a[mt][0], a[mt][1], a[mt][2], a[mt][3],
                        abuf + abase[mt] + ((((uint32_t)(2 * k8) + agsel) ^ asw[mt]) << 4));
            #pragma unroll
            for (int p = 0; p < 2; p++)
                ldsm_x4(b[2*p][0], b[2*p][1], b[2*p+1][0], b[2*p+1][1],
                        bbuf + bbase[p] + ((((uint32_t)(2 * k8) + bg0) ^ bsw[p]) << 4));
            #pragma unroll
            for (int mt = 0; mt < 4; mt++)
                #pragma unroll
                for (int nt = 0; nt < 4; nt++)
                    mma_tf32(c[mt][nt], a[mt], b[nt]);
        }

        if (i + 2 < NC) load_tile((i + 2) << 5, (i + 2) % 3);
    }

    // epilogue
    #pragma unroll
    for (int mt = 0; mt < 4; mt++) {
        int r0 = bm + wm * 64 + mt * 16 + g;
        #pragma unroll
        for (int nt = 0; nt < 4; nt++) {
            int col = bn + wn * 32 + nt * 8 + 2 * t;
            float bx = 0.f, by = 0.f;
            if (bias) { bx = __ldg(bias + col); by = __ldg(bias + col + 1); }
            #pragma unroll
            for (int half = 0; half < 2; half++) {
                int r = r0 + half * 8;
                float vx = c[mt][nt][half * 2 + 0] + bx;
                float vy = c[mt][nt][half * 2 + 1] + by;
                if (SILU) {
                    vx = vx / (1.0f + __expf(-vx));
                    vy = vy / (1.0f + __expf(-vy));
                }
                if (RES) {
                    float2 rr = *(const float2*)(res + (size_t)r * NN + col);
                    vx += rr.x; vy += rr.y;
                }
                if (ROUND) { vx = tf32_rna(vx); vy = tf32_rna(vy); }
                *(float2*)(C + (size_t)r * NN + col) = make_float2(vx, vy);
            }
        }
    }
}

// ---------------------------------------------------------------------------
// SiLU attention v2 (R14, cycle-validated): S in [i][j] orientation; P stays
// in registers via in-warp fragment transpose. ONE barrier per j-tile.
// Each warp owns [16i x 32j]; partial O reduced cross-warp at the end.
// smem (floats, stride 68): KS0 KS1 VT0 VT1 QS RED, each 64x68
// ---------------------------------------------------------------------------
#define KS0_F 0
#define KS1_F 4352
#define VT0_F 8704
#define VT1_F 13056
#define QS_F  17408
#define RED_F 21760
#define ATT_SMEM (26112 * 4)   // 104448 B; 2 CTAs/SM

__global__ void __launch_bounds__(256, 2) attn_mma()
{
    extern __shared__ float sm[];
    uint32_t sbase = smem_u32(sm);
    int bi = (int)gridDim.x - 1 - (int)blockIdx.x;   // longest CTAs first
    int h = blockIdx.y, b = blockIdx.z;
    int tid = threadIdx.x, wid = tid >> 5, lane = tid & 31;
    int g = lane >> 2, t = lane & 3;
    int wI = wid >> 1, wJ = wid & 1;
    const int qoff = 1024 + h * 64;
    const int koff = 1536 + h * 64;
    const int ibase = bi * 64;
    const size_t rowb = (size_t)b * SS;
    const size_t vtb  = (size_t)(b * HH + h) * 64;
    const float invS = 1.0f / (float)SS;

    uint32_t a_q   = lda_off(wI * 16, 68, lane);         // Q rows i
    uint32_t b_k0  = ldb_off(wJ * 32,      68, lane);    // K rows j
    uint32_t b_k1  = ldb_off(wJ * 32 + 16, 68, lane);
    uint32_t b_v[4];
    #pragma unroll
    for (int p = 0; p < 4; p++) b_v[p] = ldb_off(p * 16, 68, lane);  // V^T rows d
    const uint32_t pv_kbase = (uint32_t)(wJ * 128);

    auto load_kv = [&](int jbase, int buf) {
        uint32_t kb = sbase + (buf ? KS1_F : KS0_F) * 4;
        uint32_t vb = sbase + (buf ? VT1_F : VT0_F) * 4;
        #pragma unroll
        for (int p = 0; p < 4; p++) {
            int idx = tid + p * 256;
            int row = idx >> 4, c16 = idx & 15;
            CP_ASYNC16(kb + row * 272 + c16 * 16,
                       g_mix + (rowb + jbase + row) * (size_t)N4 + koff + c16 * 4);
            CP_ASYNC16(vb + row * 272 + c16 * 16,
                       g_vT + (vtb + row) * SS + jbase + c16 * 4);
        }
        CP_COMMIT();
    };

    load_kv(0, 0);
    {
        uint32_t qb = sbase + QS_F * 4;
        #pragma unroll
        for (int p = 0; p < 4; p++) {
            int idx = tid + p * 256;
            int row = idx >> 4, c16 = idx & 15;
            CP_ASYNC16(qb + row * 272 + c16 * 16,
                       g_mix + (rowb + ibase + row) * (size_t)N4 + qoff + c16 * 4);
        }
        CP_COMMIT();
    }

    float o[8][4];
    #pragma unroll
    for (int nt = 0; nt < 8; nt++)
        #pragma unroll
        for (int e = 0; e < 4; e++) o[nt][e] = 0.0f;

    for (int jt = 0; jt <= bi; jt++) {
        int jbase = jt * 64;
        int cur = jt & 1;
        uint32_t ksb = sbase + (cur ? KS1_F : KS0_F) * 4;
        uint32_t vsb = sbase + (cur ? VT1_F : VT0_F) * 4;
        uint32_t qsb = sbase + QS_F * 4;

        CP_WAIT0();
        __syncthreads();

        if (jt < bi) load_kv(jbase + 64, cur ^ 1);

        // QK
        float c[4][4];
        #pragma unroll
        for (int nt = 0; nt < 4; nt++)
            #pragma unroll
            for (int e = 0; e < 4; e++) c[nt][e] = 0.0f;

        #pragma unroll
        for (int k8 = 0; k8 < 8; k8++) {
            uint32_t kb = k8 * 32;
            uint32_t a[4], bfr[4][2];
            ldsm_x4(a[0], a[1], a[2], a[3], qsb + a_q + kb);
            ldsm_x4(bfr[0][0], bfr[0][1], bfr[1][0], bfr[1][1], ksb + b_k0 + kb);
            ldsm_x4(bfr[2][0], bfr[2][1], bfr[3][0], bfr[3][1], ksb + b_k1 + kb);
            #pragma unroll
            for (int nt = 0; nt < 4; nt++)
                mma_tf32(c[nt], a, bfr[nt]);
        }

        // silu + mask, P in registers
        bool diag = (jt == bi);
        #pragma unroll
        for (int nt = 0; nt < 4; nt++) {
            #pragma unroll
            for (int e = 0; e < 4; e++) {
                float z = c[nt][e] * ALPHA;
                float sv = z / (1.0f + __expf(-z)) * invS;
                if (diag) {
                    int gi = ibase + wI * 16 + g + (e >> 1) * 8;
                    int gj = jbase + wJ * 32 + nt * 8 + 2 * t + (e & 1);
                    bool valid = (gj <= gi) && ((gj < SS - NT) || (gi == gj));
                    sv = valid ? sv : 0.0f;
                }
                c[nt][e] = tf32_rna(sv);
            }
        }

        // PV
        #pragma unroll
        for (int nt = 0; nt < 4; nt++) {
            uint32_t a[4];
            acc_to_afrag(a, c[nt], lane);
            uint32_t kb = pv_kbase + nt * 32;
            uint32_t bfr[8][2];
            #pragma unroll
            for (int p = 0; p < 4; p++)
                ldsm_x4(bfr[2*p][0], bfr[2*p][1], bfr[2*p+1][0], bfr[2*p+1][1],
                        vsb + b_v[p] + kb);
            #pragma unroll
            for (int dt = 0; dt < 8; dt++)
                mma_tf32(o[dt], a, bfr[dt]);
        }
    }

    // cross-warp O reduction
    __syncthreads();
    if (wJ == 1) {
        #pragma unroll
        for (int dt = 0; dt < 8; dt++)
            #pragma unroll
            for (int half = 0; half < 2; half++)
                *(float2*)(sm + RED_F + (wI * 16 + g + half * 8) * 68
                           + dt * 8 + 2 * t) =
                    make_float2(o[dt][half * 2 + 0], o[dt][half * 2 + 1]);
    }
    __syncthreads();
    if (wJ == 0) {
        #pragma unroll
        for (int dt = 0; dt < 8; dt++) {
            int col = h * 64 + dt * 8 + 2 * t;
            #pragma unroll
            for (int half = 0; half < 2; half++) {
                float2 r2 = *(const float2*)(sm + RED_F +
                             (wI * 16 + g + half * 8) * 68 + dt * 8 + 2 * t);
                size_t r = rowb + ibase + wI * 16 + g + half * 8;
                *(float2*)(g_att + r * EE + col) =
                    make_float2(o[dt][half * 2 + 0] + r2.x,
                                o[dt][half * 2 + 1] + r2.y);
            }
        }
    }
}

// ---------------------------------------------------------------------------
extern "C" void kernel_launch(void* const* d_in, const int* in_sizes, int n_in,
                              void* d_out, int out_size)
{
    const float* x       = (const float*)d_in[0];
    const float* w_uvqk  = (const float*)d_in[1];
    const float* b_uvqk  = (const float*)d_in[2];
    const float* ln_in_w = (const float*)d_in[3];
    const float* ln_in_b = (const float*)d_in[4];
    const float* ln_o_w  = (const float*)d_in[5];
    const float* ln_o_b  = (const float*)d_in[6];
    const float* w_proj  = (const float*)d_in[7];
    float* out = (float*)d_out;

    float *xn, *mix, *att, *par, *wuT, *wpT;
    cudaGetSymbolAddress((void**)&xn,  g_xn);
    cudaGetSymbolAddress((void**)&mix, g_mix);
    cudaGetSymbolAddress((void**)&att, g_att);
    cudaGetSymbolAddress((void**)&par, g_par);
    cudaGetSymbolAddress((void**)&wuT, g_wuT);
    cudaGetSymbolAddress((void**)&wpT, g_wpT);

    cudaFuncSetAttribute(gemm_mma<true, false, true, N4, EE>,
                         cudaFuncAttributeMaxDynamicSharedMemorySize, GEMM_SMEM);
    cudaFuncSetAttribute(gemm_mma<false, true, false, EE, EE>,
                         cudaFuncAttributeMaxDynamicSharedMemorySize, GEMM_SMEM);
    cudaFuncSetAttribute(attn_mma,
                         cudaFuncAttributeMaxDynamicSharedMemorySize, ATT_SMEM);

    // weight transposes (tf32-rounded)
    {
        dim3 b32(32, 8);
        transpose_kernel<<<dim3(N4 / 32, EE / 32), b32>>>(w_uvqk, wuT, EE, N4);
        transpose_kernel<<<dim3(EE / 32, EE / 32), b32>>>(w_proj, wpT, EE, EE);
    }

    // 1) input LN
    ln_in_kernel<<<TT, 128>>>(x, ln_in_w, ln_in_b, xn);

    // 2) mixed = silu(xn @ w_uvqk + b)  -> tf32-rounded
    {
        dim3 grid(N4 / 128, TT / 128);
        gemm_mma<true, false, true, N4, EE><<<grid, 256, GEMM_SMEM>>>(
            xn, wuT, b_uvqk, nullptr, mix);
    }

    // 2b) v transpose for attention PV ldmatrix
    {
        dim3 b32(32, 8);
        vt_kernel<<<dim3(SS / 32, 2, BB * HH), b32>>>();
    }

    // 3) attention
    {
        dim3 grid(SS / 64, HH, BB);
        attn_mma<<<grid, 256, ATT_SMEM>>>();
    }

    // 4) parallel = u * LN(attn_out)
    ln_mul_kernel<<<TT, 128>>>(att, ln_o_w, ln_o_b, par);

    // 5) out = parallel @ w_proj + x
    {
        dim3 grid(EE / 128, TT / 128);
        gemm_mma<false, true, false, EE, EE><<<grid, 256, GEMM_SMEM>>>(
            par, wpT, nullptr, x, out);
    }
}

// round 16
// speedup vs baseline: 1.8656x; 1.1262x over previous
#include <cuda_runtime.h>
#include <math.h>
#include <stdint.h>

// Problem constants (fixed: B=8, S=2048, H=8, D=64)
#define TT   16384
#define EE   512
#define HH   8
#define SS   2048
#define BB   8
#define NT   64
#define N4   2048
#define ALPHA 0.125f

// Scratch
__device__ float g_xn  [TT * EE];
__device__ float g_mix [TT * N4];
__device__ float g_att [TT * EE];
__device__ float g_par [TT * EE];
__device__ float g_wuT [N4 * EE];
__device__ float g_wpT [EE * EE];
__device__ float g_vT  [BB * HH * 64 * SS];   // V transposed: [(b,h,d)][s]

// ---------------------------------------------------------------------------
__device__ __forceinline__ uint32_t smem_u32(const void* p) {
    uint32_t a;
    asm("{ .reg .u64 t; cvta.to.shared.u64 t, %1; cvt.u32.u64 %0, t; }"
        : "=r"(a) : "l"(p));
    return a;
}
__device__ __forceinline__ float tf32_rna(float x) {
    uint32_t u = __float_as_uint(x);
    asm("cvt.rna.tf32.f32 %0, %1;" : "=r"(u) : "r"(u));
    return __uint_as_float(u);
}
// silu via single-MUFU tanh: z*sigmoid(z) = 0.5*z*(1 + tanh(z/2))
__device__ __forceinline__ float silu_fast(float z) {
    float th;
    asm("tanh.approx.f32 %0, %1;" : "=f"(th) : "f"(z * 0.5f));
    return fmaf(0.5f * z, th, 0.5f * z);
}
__device__ __forceinline__ void mma_tf32(float* c, const uint32_t* a, const uint32_t* b) {
    asm volatile(
        "mma.sync.aligned.m16n8k8.row.col.f32.tf32.tf32.f32 "
        "{%0,%1,%2,%3}, {%4,%5,%6,%7}, {%8,%9}, {%0,%1,%2,%3};"
        : "+f"(c[0]), "+f"(c[1]), "+f"(c[2]), "+f"(c[3])
        : "r"(a[0]), "r"(a[1]), "r"(a[2]), "r"(a[3]), "r"(b[0]), "r"(b[1]));
}
__device__ __forceinline__ void ldsm_x4(uint32_t& r0, uint32_t& r1,
                                        uint32_t& r2, uint32_t& r3, uint32_t addr) {
    asm volatile("ldmatrix.sync.aligned.m8n8.x4.shared.b16 {%0,%1,%2,%3}, [%4];"
                 : "=r"(r0), "=r"(r1), "=r"(r2), "=r"(r3) : "r"(addr));
}
#define CP_ASYNC16(s, g) asm volatile("cp.async.cg.shared.global [%0], [%1], 16;" :: "r"(s), "l"(g))
#define CP_COMMIT()      asm volatile("cp.async.commit_group;")
#define CP_WAIT1()       asm volatile("cp.async.wait_group 1;" ::: "memory")
#define CP_WAIT0()       asm volatile("cp.async.wait_group 0;" ::: "memory")

// ldmatrix lane offsets for padded-stride tiles, stride in floats
__device__ __forceinline__ uint32_t lda_off(int baserow, int stride, int lane) {
    int r15 = lane & 15, c4 = (lane >> 4) * 4;
    return (uint32_t)(((baserow + r15) * stride + c4) * 4);
}
__device__ __forceinline__ uint32_t ldb_off(int baserow, int stride, int lane) {
    int r7 = lane & 7, sel = lane >> 3;
    return (uint32_t)(((baserow + r7 + (sel >> 1) * 8) * stride + (sel & 1) * 4) * 4);
}

// Accumulator (16x8, [g][2t]) -> A-fragment ([g][t],[g][t+4]) in-warp transpose.
__device__ __forceinline__ void acc_to_afrag(uint32_t* a, const float* c, int lane) {
    int srcA = (lane & 28) | ((lane & 3) >> 1);
    int srcB = srcA + 2;
    bool odd = (lane & 1);
    float v00 = __shfl_sync(0xffffffffu, c[0], srcA);
    float v01 = __shfl_sync(0xffffffffu, c[1], srcA);
    float v02 = __shfl_sync(0xffffffffu, c[2], srcA);
    float v03 = __shfl_sync(0xffffffffu, c[3], srcA);
    float v10 = __shfl_sync(0xffffffffu, c[0], srcB);
    float v11 = __shfl_sync(0xffffffffu, c[1], srcB);
    float v12 = __shfl_sync(0xffffffffu, c[2], srcB);
    float v13 = __shfl_sync(0xffffffffu, c[3], srcB);
    a[0] = __float_as_uint(odd ? v01 : v00);
    a[1] = __float_as_uint(odd ? v03 : v02);
    a[2] = __float_as_uint(odd ? v11 : v10);
    a[3] = __float_as_uint(odd ? v13 : v12);
}

// ---------------------------------------------------------------------------
// Weight transpose + tf32 rounding: dst[n][k] = rna(src[k][n])
// ---------------------------------------------------------------------------
__global__ void transpose_kernel(const float* __restrict__ src,
                                 float* __restrict__ dst, int K, int N)
{
    __shared__ float t[32][33];
    int n0 = blockIdx.x * 32, k0 = blockIdx.y * 32;
    int tx = threadIdx.x, ty = threadIdx.y;
    #pragma unroll
    for (int j = 0; j < 4; j++)
        t[ty + j * 8][tx] = src[(size_t)(k0 + ty + j * 8) * N + n0 + tx];
    __syncthreads();
    #pragma unroll
    for (int j = 0; j < 4; j++)
        dst[(size_t)(n0 + ty + j * 8) * K + k0 + tx] = tf32_rna(t[tx][ty + j * 8]);
}

// v transpose: g_vT[(b*H+h)*64 + d][s] = g_mix[b*S+s][512 + h*64 + d]
__global__ void vt_kernel()
{
    __shared__ float t[32][33];
    int bh = blockIdx.z;
    int s0 = blockIdx.x * 32, d0 = blockIdx.y * 32;
    int tx = threadIdx.x, ty = threadIdx.y;
    int b = bh >> 3, h = bh & 7;
    #pragma unroll
    for (int j = 0; j < 4; j++)
        t[ty + j * 8][tx] =
            g_mix[(size_t)(b * SS + s0 + ty + j * 8) * N4 + 512 + h * 64 + d0 + tx];
    __syncthreads();
    #pragma unroll
    for (int j = 0; j < 4; j++)
        g_vT[(size_t)(bh * 64 + d0 + ty + j * 8) * SS + s0 + tx] = t[tx][ty + j * 8];
}

// ---------------------------------------------------------------------------
// LayerNorm kernels (tf32-rounded outputs)
// ---------------------------------------------------------------------------
__global__ void ln_in_kernel(const float* __restrict__ x,
                             const float* __restrict__ w,
                             const float* __restrict__ b,
                             float* __restrict__ out)
{
    int row = blockIdx.x;
    int tid = threadIdx.x;
    const float4* xr = (const float4*)(x + (size_t)row * EE);
    float4 v = xr[tid];
    float s  = v.x + v.y + v.z + v.w;
    float s2 = v.x*v.x + v.y*v.y + v.z*v.z + v.w*v.w;
    #pragma unroll
    for (int off = 16; off; off >>= 1) {
        s  += __shfl_xor_sync(0xffffffffu, s,  off);
        s2 += __shfl_xor_sync(0xffffffffu, s2, off);
    }
    __shared__ float sb[4], sb2[4];
    int wid = tid >> 5, lane = tid & 31;
    if (lane == 0) { sb[wid] = s; sb2[wid] = s2; }
    __syncthreads();
    float tot  = sb[0] + sb[1] + sb[2] + sb[3];
    float tot2 = sb2[0] + sb2[1] + sb2[2] + sb2[3];
    float mu  = tot * (1.0f / EE);
    float var = tot2 * (1.0f / EE) - mu * mu;
    float rstd = rsqrtf(var + 1e-5f);
    float4 w4 = ((const float4*)w)[tid];
    float4 b4 = ((const float4*)b)[tid];
    float4 o;
    o.x = tf32_rna((v.x - mu) * rstd * w4.x + b4.x);
    o.y = tf32_rna((v.y - mu) * rstd * w4.y + b4.y);
    o.z = tf32_rna((v.z - mu) * rstd * w4.z + b4.z);
    o.w = tf32_rna((v.w - mu) * rstd * w4.w + b4.w);
    ((float4*)(out + (size_t)row * EE))[tid] = o;
}

__global__ void ln_mul_kernel(const float* __restrict__ a,
                              const float* __restrict__ w,
                              const float* __restrict__ b,
                              float* __restrict__ out)
{
    int row = blockIdx.x;
    int tid = threadIdx.x;
    const float4* xr = (const float4*)(a + (size_t)row * EE);
    float4 v = xr[tid];
    float s  = v.x + v.y + v.z + v.w;
    float s2 = v.x*v.x + v.y*v.y + v.z*v.z + v.w*v.w;
    #pragma unroll
    for (int off = 16; off; off >>= 1) {
        s  += __shfl_xor_sync(0xffffffffu, s,  off);
        s2 += __shfl_xor_sync(0xffffffffu, s2, off);
    }
    __shared__ float sb[4], sb2[4];
    int wid = tid >> 5, lane = tid & 31;
    if (lane == 0) { sb[wid] = s; sb2[wid] = s2; }
    __syncthreads();
    float tot  = sb[0] + sb[1] + sb[2] + sb[3];
    float tot2 = sb2[0] + sb2[1] + sb2[2] + sb2[3];
    float mu  = tot * (1.0f / EE);
    float var = tot2 * (1.0f / EE) - mu * mu;
    float rstd = rsqrtf(var + 1e-5f);
    float4 w4 = ((const float4*)w)[tid];
    float4 b4 = ((const float4*)b)[tid];
    float4 u4 = ((const float4*)(g_mix + (size_t)row * N4))[tid];
    float4 o;
    o.x = tf32_rna(u4.x * ((v.x - mu) * rstd * w4.x + b4.x));
    o.y = tf32_rna(u4.y * ((v.y - mu) * rstd * w4.y + b4.y));
    o.z = tf32_rna(u4.z * ((v.z - mu) * rstd * w4.z + b4.z));
    o.w = tf32_rna(u4.w * ((v.w - mu) * rstd * w4.w + b4.w));
    ((float4*)(out + (size_t)row * EE))[tid] = o;
}

// ---------------------------------------------------------------------------
// mma.sync tf32 GEMM (R15, proven): swizzled 3-stage, compile-time unroll.
// ---------------------------------------------------------------------------
#define GSTAGE_B 32768
#define GEMM_SMEM (3 * GSTAGE_B)    // 98304 B -> 2 CTAs/SM

template<bool SILU, bool RES, bool ROUND, int NN, int KK>
__global__ void __launch_bounds__(256, 2)
gemm_mma(const float* __restrict__ A, const float* __restrict__ Bt,
         const float* __restrict__ bias, const float* __restrict__ res,
         float* __restrict__ C)
{
    extern __shared__ float sm[];
    uint32_t sbase = smem_u32(sm);
    int tid = threadIdx.x;
    int wid = tid >> 5, lane = tid & 31;
    int g = lane >> 2, t = lane & 3;
    int wm = wid >> 2, wn = wid & 3;
    int bm = blockIdx.y * 128, bn = blockIdx.x * 128;
    constexpr int NC = KK >> 5;

    uint32_t abase[4], asw[4];
    uint32_t agsel = (uint32_t)(lane >> 4);
    #pragma unroll
    for (int mt = 0; mt < 4; mt++) {
        int r = wm * 64 + mt * 16 + (lane & 15);
        abase[mt] = (uint32_t)(r * 128);
        asw[mt]   = (uint32_t)(r & 7);
    }
    uint32_t bbase[2], bsw[2], bg0;
    {
        int sel = lane >> 3;
        bg0 = (uint32_t)(sel & 1);
        #pragma unroll
        for (int p = 0; p < 2; p++) {
            int r = wn * 32 + p * 16 + (lane & 7) + ((sel >> 1) * 8);
            bbase[p] = (uint32_t)(r * 128);
            bsw[p]   = (uint32_t)(r & 7);
        }
    }

    float c[4][4][4];
    #pragma unroll
    for (int i = 0; i < 4; i++)
        #pragma unroll
        for (int j = 0; j < 4; j++)
            #pragma unroll
            for (int e = 0; e < 4; e++) c[i][j][e] = 0.0f;

    auto load_tile = [&](int koff, int stage) {
        uint32_t ab = sbase + stage * GSTAGE_B;
        uint32_t bb = ab + 16384;
        #pragma unroll
        for (int p = 0; p < 4; p++) {
            int idx = tid + p * 256;
            int row = idx >> 3, c16 = idx & 7;
            uint32_t so = (uint32_t)(row * 128 + ((c16 ^ (row & 7)) << 4));
            CP_ASYNC16(ab + so, A + (size_t)(bm + row) * KK + koff + c16 * 4);
        }
        #pragma unroll
        for (int p = 0; p < 4; p++) {
            int idx = tid + p * 256;
            int row = idx >> 3, c16 = idx & 7;
            uint32_t so = (uint32_t)(row * 128 + ((c16 ^ (row & 7)) << 4));
            CP_ASYNC16(bb + so, Bt + (size_t)(bn + row) * KK + koff + c16 * 4);
        }
        CP_COMMIT();
    };

    load_tile(0, 0);
    load_tile(32, 1);

    #pragma unroll
    for (int i = 0; i < NC; i++) {
        const int stage = i % 3;
        if (i + 1 < NC) CP_WAIT1(); else CP_WAIT0();
        __syncthreads();

        uint32_t abuf = sbase + stage * GSTAGE_B;
        uint32_t bbuf = abuf + 16384;

        #pragma unroll
        for (int k8 = 0; k8 < 4; k8++) {
            uint32_t a[4][4], b[4][2];
            #pragma unroll
            for (int mt = 0; mt < 4; mt++)
                ldsm_x4(a[mt][0], a[mt][1], a[mt][2], a[mt][3],
                        abuf + abase[mt] + ((((uint32_t)(2 * k8) + agsel) ^ asw[mt]) << 4));
            #pragma unroll
            for (int p = 0; p < 2; p++)
                ldsm_x4(b[2*p][0], b[2*p][1], b[2*p+1][0], b[2*p+1][1],
                        bbuf + bbase[p] + ((((uint32_t)(2 * k8) + bg0) ^ bsw[p]) << 4));
            #pragma unroll
            for (int mt = 0; mt < 4; mt++)
                #pragma unroll
                for (int nt = 0; nt < 4; nt++)
                    mma_tf32(c[mt][nt], a[mt], b[nt]);
        }

        if (i + 2 < NC) load_tile((i + 2) << 5, (i + 2) % 3);
    }

    // epilogue
    #pragma unroll
    for (int mt = 0; mt < 4; mt++) {
        int r0 = bm + wm * 64 + mt * 16 + g;
        #pragma unroll
        for (int nt = 0; nt < 4; nt++) {
            int col = bn + wn * 32 + nt * 8 + 2 * t;
            float bx = 0.f, by = 0.f;
            if (bias) { bx = __ldg(bias + col); by = __ldg(bias + col + 1); }
            #pragma unroll
            for (int half = 0; half < 2; half++) {
                int r = r0 + half * 8;
                float vx = c[mt][nt][half * 2 + 0] + bx;
                float vy = c[mt][nt][half * 2 + 1] + by;
                if (SILU) {
                    vx = silu_fast(vx);
                    vy = silu_fast(vy);
                }
                if (RES) {
                    float2 rr = *(const float2*)(res + (size_t)r * NN + col);
                    vx += rr.x; vy += rr.y;
                }
                if (ROUND) { vx = tf32_rna(vx); vy = tf32_rna(vy); }
                *(float2*)(C + (size_t)r * NN + col) = make_float2(vx, vy);
            }
        }
    }
}

// ---------------------------------------------------------------------------
// SiLU attention v2 (R14/R15 structure) + single-MUFU silu (tanh.approx).
// smem (floats, stride 68): KS0 KS1 VT0 VT1 QS RED, each 64x68
// ---------------------------------------------------------------------------
#define KS0_F 0
#define KS1_F 4352
#define VT0_F 8704
#define VT1_F 13056
#define QS_F  17408
#define RED_F 21760
#define ATT_SMEM (26112 * 4)   // 104448 B; 2 CTAs/SM

__global__ void __launch_bounds__(256, 2) attn_mma()
{
    extern __shared__ float sm[];
    uint32_t sbase = smem_u32(sm);
    int bi = (int)gridDim.x - 1 - (int)blockIdx.x;   // longest CTAs first
    int h = blockIdx.y, b = blockIdx.z;
    int tid = threadIdx.x, wid = tid >> 5, lane = tid & 31;
    int g = lane >> 2, t = lane & 3;
    int wI = wid >> 1, wJ = wid & 1;
    const int qoff = 1024 + h * 64;
    const int koff = 1536 + h * 64;
    const int ibase = bi * 64;
    const size_t rowb = (size_t)b * SS;
    const size_t vtb  = (size_t)(b * HH + h) * 64;
    const float invS = 1.0f / (float)SS;

    uint32_t a_q   = lda_off(wI * 16, 68, lane);
    uint32_t b_k0  = ldb_off(wJ * 32,      68, lane);
    uint32_t b_k1  = ldb_off(wJ * 32 + 16, 68, lane);
    uint32_t b_v[4];
    #pragma unroll
    for (int p = 0; p < 4; p++) b_v[p] = ldb_off(p * 16, 68, lane);
    const uint32_t pv_kbase = (uint32_t)(wJ * 128);

    auto load_kv = [&](int jbase, int buf) {
        uint32_t kb = sbase + (buf ? KS1_F : KS0_F) * 4;
        uint32_t vb = sbase + (buf ? VT1_F : VT0_F) * 4;
        #pragma unroll
        for (int p = 0; p < 4; p++) {
            int idx = tid + p * 256;
            int row = idx >> 4, c16 = idx & 15;
            CP_ASYNC16(kb + row * 272 + c16 * 16,
                       g_mix + (rowb + jbase + row) * (size_t)N4 + koff + c16 * 4);
            CP_ASYNC16(vb + row * 272 + c16 * 16,
                       g_vT + (vtb + row) * SS + jbase + c16 * 4);
        }
        CP_COMMIT();
    };

    load_kv(0, 0);
    {
        uint32_t qb = sbase + QS_F * 4;
        #pragma unroll
        for (int p = 0; p < 4; p++) {
            int idx = tid + p * 256;
            int row = idx >> 4, c16 = idx & 15;
            CP_ASYNC16(qb + row * 272 + c16 * 16,
                       g_mix + (rowb + ibase + row) * (size_t)N4 + qoff + c16 * 4);
        }
        CP_COMMIT();
    }

    float o[8][4];
    #pragma unroll
    for (int nt = 0; nt < 8; nt++)
        #pragma unroll
        for (int e = 0; e < 4; e++) o[nt][e] = 0.0f;

    for (int jt = 0; jt <= bi; jt++) {
        int jbase = jt * 64;
        int cur = jt & 1;
        uint32_t ksb = sbase + (cur ? KS1_F : KS0_F) * 4;
        uint32_t vsb = sbase + (cur ? VT1_F : VT0_F) * 4;
        uint32_t qsb = sbase + QS_F * 4;

        CP_WAIT0();
        __syncthreads();

        if (jt < bi) load_kv(jbase + 64, cur ^ 1);

        // QK
        float c[4][4];
        #pragma unroll
        for (int nt = 0; nt < 4; nt++)
            #pragma unroll
            for (int e = 0; e < 4; e++) c[nt][e] = 0.0f;

        #pragma unroll
        for (int k8 = 0; k8 < 8; k8++) {
            uint32_t kb = k8 * 32;
            uint32_t a[4], bfr[4][2];
            ldsm_x4(a[0], a[1], a[2], a[3], qsb + a_q + kb);
            ldsm_x4(bfr[0][0], bfr[0][1], bfr[1][0], bfr[1][1], ksb + b_k0 + kb);
            ldsm_x4(bfr[2][0], bfr[2][1], bfr[3][0], bfr[3][1], ksb + b_k1 + kb);
            #pragma unroll
            for (int nt = 0; nt < 4; nt++)
                mma_tf32(c[nt], a, bfr[nt]);
        }

        // silu (single MUFU) + mask, P in registers
        bool diag = (jt == bi);
        #pragma unroll
        for (int nt = 0; nt < 4; nt++) {
            #pragma unroll
            for (int e = 0; e < 4; e++) {
                float z = c[nt][e] * ALPHA;
                float sv = silu_fast(z) * invS;
                if (diag) {
                    int gi = ibase + wI * 16 + g + (e >> 1) * 8;
                    int gj = jbase + wJ * 32 + nt * 8 + 2 * t + (e & 1);
                    bool valid = (gj <= gi) && ((gj < SS - NT) || (gi == gj));
                    sv = valid ? sv : 0.0f;
                }
                c[nt][e] = tf32_rna(sv);
            }
        }

        // PV
        #pragma unroll
        for (int nt = 0; nt < 4; nt++) {
            uint32_t a[4];
            acc_to_afrag(a, c[nt], lane);
            uint32_t kb = pv_kbase + nt * 32;
            uint32_t bfr[8][2];
            #pragma unroll
            for (int p = 0; p < 4; p++)
                ldsm_x4(bfr[2*p][0], bfr[2*p][1], bfr[2*p+1][0], bfr[2*p+1][1],
                        vsb + b_v[p] + kb);
            #pragma unroll
            for (int dt = 0; dt < 8; dt++)
                mma_tf32(o[dt], a, bfr[dt]);
        }
    }

    // cross-warp O reduction
    __syncthreads();
    if (wJ == 1) {
        #pragma unroll
        for (int dt = 0; dt < 8; dt++)
            #pragma unroll
            for (int half = 0; half < 2; half++)
                *(float2*)(sm + RED_F + (wI * 16 + g + half * 8) * 68
                           + dt * 8 + 2 * t) =
                    make_float2(o[dt][half * 2 + 0], o[dt][half * 2 + 1]);
    }
    __syncthreads();
    if (wJ == 0) {
        #pragma unroll
        for (int dt = 0; dt < 8; dt++) {
            int col = h * 64 + dt * 8 + 2 * t;
            #pragma unroll
            for (int half = 0; half < 2; half++) {
                float2 r2 = *(const float2*)(sm + RED_F +
                             (wI * 16 + g + half * 8) * 68 + dt * 8 + 2 * t);
                size_t r = rowb + ibase + wI * 16 + g + half * 8;
                *(float2*)(g_att + r * EE + col) =
                    make_float2(o[dt][half * 2 + 0] + r2.x,
                                o[dt][half * 2 + 1] + r2.y);
            }
        }
    }
}

// ---------------------------------------------------------------------------
extern "C" void kernel_launch(void* const* d_in, const int* in_sizes, int n_in,
                              void* d_out, int out_size)
{
    const float* x       = (const float*)d_in[0];
    const float* w_uvqk  = (const float*)d_in[1];
    const float* b_uvqk  = (const float*)d_in[2];
    const float* ln_in_w = (const float*)d_in[3];
    const float* ln_in_b = (const float*)d_in[4];
    const float* ln_o_w  = (const float*)d_in[5];
    const float* ln_o_b  = (const float*)d_in[6];
    const float* w_proj  = (const float*)d_in[7];
    float* out = (float*)d_out;

    float *xn, *mix, *att, *par, *wuT, *wpT;
    cudaGetSymbolAddress((void**)&xn,  g_xn);
    cudaGetSymbolAddress((void**)&mix, g_mix);
    cudaGetSymbolAddress((void**)&att, g_att);
    cudaGetSymbolAddress((void**)&par, g_par);
    cudaGetSymbolAddress((void**)&wuT, g_wuT);
    cudaGetSymbolAddress((void**)&wpT, g_wpT);

    cudaFuncSetAttribute(gemm_mma<true, false, true, N4, EE>,
                         cudaFuncAttributeMaxDynamicSharedMemorySize, GEMM_SMEM);
    cudaFuncSetAttribute(gemm_mma<false, true, false, EE, EE>,
                         cudaFuncAttributeMaxDynamicSharedMemorySize, GEMM_SMEM);
    cudaFuncSetAttribute(attn_mma,
                         cudaFuncAttributeMaxDynamicSharedMemorySize, ATT_SMEM);

    // weight transposes (tf32-rounded)
    {
        dim3 b32(32, 8);
        transpose_kernel<<<dim3(N4 / 32, EE / 32), b32>>>(w_uvqk, wuT, EE, N4);
        transpose_kernel<<<dim3(EE / 32, EE / 32), b32>>>(w_proj, wpT, EE, EE);
    }

    // 1) input LN
    ln_in_kernel<<<TT, 128>>>(x, ln_in_w, ln_in_b, xn);

    // 2) mixed = silu(xn @ w_uvqk + b)  -> tf32-rounded
    {
        dim3 grid(N4 / 128, TT / 128);
        gemm_mma<true, false, true, N4, EE><<<grid, 256, GEMM_SMEM>>>(
            xn, wuT, b_uvqk, nullptr, mix);
    }

    // 2b) v transpose for attention PV ldmatrix
    {
        dim3 b32(32, 8);
        vt_kernel<<<dim3(SS / 32, 2, BB * HH), b32>>>();
    }

    // 3) attention
    {
        dim3 grid(SS / 64, HH, BB);
        attn_mma<<<grid, 256, ATT_SMEM>>>();
    }

    // 4) parallel = u * LN(attn_out)
    ln_mul_kernel<<<TT, 128>>>(att, ln_o_w, ln_o_b, par);

    // 5) out = parallel @ w_proj + x
    {
        dim3 grid(EE / 128, TT / 128);
        gemm_mma<false, true, false, EE, EE><<<grid, 256, GEMM_SMEM>>>(
            par, wpT, nullptr, x, out);
    }
}